// round 3
// baseline (speedup 1.0000x reference)
#include <cuda_runtime.h>
#include <cuda_fp16.h>
#include <stdint.h>
#include <math.h>

// BlockCirculant via FFT:  out = ifft( fft(x*d blocks) * conj(fft(W)) ) + bias
// B=8192 rows, D=4096, 16 blocks of 256. 2-for-1 real FFT packing,
// FFT-256 = 16x16 Cooley-Tukey with per-thread register FFT-16.

#define K16   16
#define BSZ   256
#define NF    129        // Hermitian frequencies 0..128
#define FP    132        // padded float pitch for X/Y arrays
#define DIN   4096
#define NB    8192
#define GP    272        // float2 per FFT group scratch (16*17)
#define ROWBUF (8*GP)    // 2176 float2 per buffer per row

// Wc = conj(FFT(W[i,j,:])) / 256  in half2, layout [i][j][f] pitch NF
__device__ __half2 g_Wc[K16 * K16 * NF];

__device__ __forceinline__ void cmul(float& xr, float& xi, float wr, float wi) {
    float tr = xr * wr - xi * wi;
    xi       = xr * wi + xi * wr;
    xr       = tr;
}

template <bool INV>
__device__ __forceinline__ void fft16(float* re, float* im) {
    // bit-reversal (4 bits)
    {
        float tr, ti;
#define SWP(a, b) tr = re[a]; re[a] = re[b]; re[b] = tr; \
                  ti = im[a]; im[a] = im[b]; im[b] = ti;
        SWP(1, 8) SWP(2, 4) SWP(3, 12) SWP(5, 10) SWP(7, 14) SWP(11, 13)
#undef SWP
    }
    constexpr float C1 = 0.923879532511286756f;
    constexpr float S1 = 0.382683432365089772f;
    constexpr float R  = 0.707106781186547524f;
    const float C16[8] = {1.f,  C1,  R,  S1, 0.f, -S1, -R, -C1};
    const float S16[8] = {0.f,  S1,  R,  C1, 1.f,  C1,  R,  S1};
#pragma unroll
    for (int s = 0; s < 4; ++s) {
        const int h = 1 << s;
#pragma unroll
        for (int g = 0; g < 16; g += (h << 1)) {
#pragma unroll
            for (int j = 0; j < h; ++j) {
                const int m = j << (3 - s);
                const float wr = C16[m];
                const float wi = INV ? S16[m] : -S16[m];
                const int a = g + j, b = a + h;
                float tr = re[b] * wr - im[b] * wi;
                float ti = re[b] * wi + im[b] * wr;
                re[b] = re[a] - tr; im[b] = im[a] - ti;
                re[a] += tr;        im[a] += ti;
            }
        }
    }
}

// ---------------- W_fft precompute (per launch, cheap) ----------------
__global__ void bc_wfft(const float* __restrict__ W) {
    __shared__ float2 tw[256];
    __shared__ float  wv[256];
    const int ij  = blockIdx.x;      // i*16 + j
    const int tid = threadIdx.x;
    float sv, cv;
    float ang = 6.2831853071795864769f * (float)tid * (1.0f / 256.0f);  // +sign: conj folded
    sincosf(ang, &sv, &cv);
    tw[tid] = make_float2(cv, sv);
    wv[tid] = W[ij * BSZ + tid];
    __syncthreads();
    if (tid < NF) {
        float ar = 0.f, ai = 0.f;
        for (int n = 0; n < 256; ++n) {
            float2 e = tw[(tid * n) & 255];
            ar += wv[n] * e.x;
            ai += wv[n] * e.y;
        }
        g_Wc[ij * NF + tid] = __floats2half2_rn(ar * (1.f / 256.f), ai * (1.f / 256.f));
    }
}

// ---------------- main fused kernel ----------------
__global__ void __launch_bounds__(256)
bc_main(const float* __restrict__ x, const float* __restrict__ d,
        const float* __restrict__ bias, float* __restrict__ out) {
    extern __shared__ char smem_raw[];
    __half2* Wcs = (__half2*)smem_raw;                          // 132096 B
    float2*  twf = (float2*)(smem_raw + 132096);                //   2048 B
    float*   ds  = (float*) (smem_raw + 132096 + 2048);         //  16384 B
    float2*  bufs = (float2*)(smem_raw + 150528);               //  69632 B

    const int tid = threadIdx.x;
    {
        const unsigned int* src = (const unsigned int*)g_Wc;
        unsigned int* dst = (unsigned int*)Wcs;
        for (int i2 = tid; i2 < K16 * K16 * NF; i2 += 256) dst[i2] = src[i2];
        float sv, cv;
        float ang = -6.2831853071795864769f * (float)tid * (1.0f / 256.0f);
        sincosf(ang, &sv, &cv);
        twf[tid] = make_float2(cv, sv);   // e^{-2pi i m /256}
        for (int i2 = tid; i2 < DIN; i2 += 256) ds[i2] = d[i2];
    }
    __syncthreads();

    const int rsub = tid >> 7;        // which of the 2 rows in flight
    const int t128 = tid & 127;
    const int g    = t128 >> 4;       // FFT group 0..7 (pair of blocks)
    const int t    = t128 & 15;       // lane within FFT
    float2* B0 = bufs + rsub * (2 * ROWBUF);
    float2* B1 = B0 + ROWBUF;
    float*  Xf = (float*)B1;          // Xr at j*FP+f, Xi at 2112 + j*FP+f
    float*  Yf = (float*)B0;

    float re[16], im[16];

    for (int base = blockIdx.x * 2; base < NB; base += gridDim.x * 2) {
        const int row = base + rsub;
        const float* xrow = x + (size_t)row * DIN;

        // ---- P0: load row, multiply by d, pack pairs of blocks as complex ----
#pragma unroll
        for (int it = 0; it < 32; ++it) {
            int col = t128 + (it << 7);
            float v = xrow[col] * ds[col];
            int p = col >> 9;          // group (2 blocks of 256)
            int n = col & 255;
            float* dstp = (float*)(B0 + p * GP + (n & 15) * 17 + (n >> 4));
            dstp[(col >> 8) & 1] = v;  // even block -> re, odd -> im
        }
        __syncthreads();

        // ---- P1 step1: FFT16 over n1, twiddle, transpose ----
        {
            float2* gb = B0 + g * GP;
#pragma unroll
            for (int n1 = 0; n1 < 16; ++n1) {
                float2 v = gb[t * 17 + n1];
                re[n1] = v.x; im[n1] = v.y;
            }
            fft16<false>(re, im);
            float2* ob = B1 + g * GP;
#pragma unroll
            for (int k1 = 0; k1 < 16; ++k1) {
                if (k1 > 0) {
                    float2 w = twf[(t * k1) & 255];
                    cmul(re[k1], im[k1], w.x, w.y);
                }
                ob[k1 * 17 + t] = make_float2(re[k1], im[k1]);
            }
        }
        __syncwarp();
        // ---- P1 step2: FFT16 over n2 -> Z natural order into B0 ----
        {
            float2* gb = B1 + g * GP;
#pragma unroll
            for (int n2 = 0; n2 < 16; ++n2) {
                float2 v = gb[t * 17 + n2];
                re[n2] = v.x; im[n2] = v.y;
            }
            fft16<false>(re, im);
            float2* ob = B0 + g * GP;
#pragma unroll
            for (int k2 = 0; k2 < 16; ++k2)
                ob[(k2 << 4) + t] = make_float2(re[k2], im[k2]);
        }
        __syncthreads();

        // ---- Hermitian unpack: Z -> X (two real spectra per group) ----
        for (int idx = t128; idx < 8 * NF; idx += 128) {
            int p = idx / NF;
            int f = idx - p * NF;
            float2 z1 = B0[p * GP + f];
            float2 z2 = B0[p * GP + ((256 - f) & 255)];
            float xar = 0.5f * (z1.x + z2.x);
            float xai = 0.5f * (z1.y - z2.y);
            float xbr = 0.5f * (z1.y + z2.y);
            float xbi = 0.5f * (z2.x - z1.x);
            Xf[(2 * p) * FP + f]            = xar;
            Xf[2112 + (2 * p) * FP + f]     = xai;
            Xf[(2 * p + 1) * FP + f]        = xbr;
            Xf[2112 + (2 * p + 1) * FP + f] = xbi;
        }
        __syncthreads();

        // ---- einsum: Y[i][f] = sum_j X[j][f] * Wc[i][j][f]  (Wc has conj+1/256) ----
        {
            const int f = t128;  // 0..127
            float yr[16], yi[16];
#pragma unroll
            for (int i = 0; i < 16; ++i) { yr[i] = 0.f; yi[i] = 0.f; }
#pragma unroll 4
            for (int j = 0; j < 16; ++j) {
                float xr = Xf[j * FP + f];
                float xi = Xf[2112 + j * FP + f];
#pragma unroll
                for (int i = 0; i < 16; ++i) {
                    float2 w = __half22float2(Wcs[(i * 16 + j) * NF + f]);
                    yr[i] += xr * w.x - xi * w.y;
                    yi[i] += xr * w.y + xi * w.x;
                }
            }
#pragma unroll
            for (int i = 0; i < 16; ++i) {
                Yf[i * FP + f]        = yr[i];
                Yf[2112 + i * FP + f] = yi[i];
            }
            if (t128 < 16) {  // Nyquist f=128: 16 tiny dot products
                float ar = 0.f, ai = 0.f;
#pragma unroll
                for (int j = 0; j < 16; ++j) {
                    float xr = Xf[j * FP + 128];
                    float xi = Xf[2112 + j * FP + 128];
                    float2 w = __half22float2(Wcs[(t128 * 16 + j) * NF + 128]);
                    ar += xr * w.x - xi * w.y;
                    ai += xr * w.y + xi * w.x;
                }
                Yf[t128 * FP + 128]        = ar;
                Yf[2112 + t128 * FP + 128] = ai;
            }
        }
        __syncthreads();

        // ---- P3 step1: pack pair (Hermitian extend), inverse FFT16 stage 1 ----
        {
#pragma unroll
            for (int n1 = 0; n1 < 16; ++n1) {
                int k = (n1 << 4) + t;
                float zr, zi;
                if (k <= 128) {
                    float ar = Yf[(2 * g) * FP + k];
                    float ai = Yf[2112 + (2 * g) * FP + k];
                    float br = Yf[(2 * g + 1) * FP + k];
                    float bi = Yf[2112 + (2 * g + 1) * FP + k];
                    zr = ar - bi; zi = ai + br;
                } else {
                    int kk = 256 - k;
                    float ar = Yf[(2 * g) * FP + kk];
                    float ai = Yf[2112 + (2 * g) * FP + kk];
                    float br = Yf[(2 * g + 1) * FP + kk];
                    float bi = Yf[2112 + (2 * g + 1) * FP + kk];
                    zr = ar + bi; zi = br - ai;
                }
                re[n1] = zr; im[n1] = zi;
            }
            fft16<true>(re, im);
            float2* ob = B1 + g * GP;
#pragma unroll
            for (int k1 = 0; k1 < 16; ++k1) {
                if (k1 > 0) {
                    float2 w = twf[(t * k1) & 255];
                    cmul(re[k1], im[k1], w.x, -w.y);   // conj twiddle
                }
                ob[k1 * 17 + t] = make_float2(re[k1], im[k1]);
            }
        }
        __syncwarp();
        // ---- P3 step2: inverse FFT16 stage 2, add bias, store ----
        {
            float2* gb = B1 + g * GP;
#pragma unroll
            for (int n2 = 0; n2 < 16; ++n2) {
                float2 v = gb[t * 17 + n2];
                re[n2] = v.x; im[n2] = v.y;
            }
            fft16<true>(re, im);
            float* orow = out + (size_t)row * DIN + (g << 9);
            const float* brow = bias + (g << 9);
#pragma unroll
            for (int k2 = 0; k2 < 16; ++k2) {
                int n = (k2 << 4) + t;
                orow[n]       = re[k2] + brow[n];        // even block (real part)
                orow[n + 256] = im[k2] + brow[n + 256];  // odd block (imag part)
            }
        }
        __syncthreads();  // protect B0 before next iteration's P0
    }
}

extern "C" void kernel_launch(void* const* d_in, const int* in_sizes, int n_in,
                              void* d_out, int out_size) {
    const float* x    = (const float*)d_in[0];
    const float* W    = (const float*)d_in[1];
    const float* d    = (const float*)d_in[2];
    const float* bias = (const float*)d_in[3];
    float* out = (float*)d_out;

    const size_t SMEM = 132096 + 2048 + 16384 + (size_t)4 * ROWBUF * sizeof(float2); // 220160 B
    cudaFuncSetAttribute(bc_main, cudaFuncAttributeMaxDynamicSharedMemorySize, (int)SMEM);

    bc_wfft<<<K16 * K16, 256>>>(W);
    bc_main<<<152, 256, SMEM>>>(x, d, bias, out);
    (void)in_sizes; (void)n_in; (void)out_size;
}

// round 6
// speedup vs baseline: 1.3816x; 1.3816x over previous
#include <cuda_runtime.h>
#include <cuda_fp16.h>
#include <stdint.h>
#include <math.h>

// BlockCirculant via FFT:  out = ifft( fft(x*d blocks) * conj(fft(W)) ) + bias
// 4 independent 128-thread row pipelines per CTA (named barriers), in-place
// FFT-256 (16x16 Cooley-Tukey), einsum fused with Hermitian unpack/repack,
// packed f32x2 FFMA in the einsum hot loop.

#define K16   16
#define BSZ   256
#define NF    129        // Hermitian frequencies 0..128
#define DIN   4096
#define NB    8192
#define GP    272        // float2 per FFT group scratch (16*17)
#define NSLOT 4
#define TPB   512

// Wc = conj(FFT(W[i,j,:])) / 256  in half2, layout [i][j][f] pitch NF
__device__ __half2 g_Wc[K16 * K16 * NF];

__device__ __forceinline__ void cmul(float& xr, float& xi, float wr, float wi) {
    float tr = xr * wr - xi * wi;
    xi       = xr * wi + xi * wr;
    xr       = tr;
}

// ---- packed fp32x2 helpers (Blackwell FFMA2) ----
__device__ __forceinline__ unsigned long long pk2(float lo, float hi) {
    unsigned long long r;
    asm("mov.b64 %0, {%1, %2};" : "=l"(r) : "f"(lo), "f"(hi));
    return r;
}
__device__ __forceinline__ float2 upk2(unsigned long long v) {
    float2 r;
    asm("mov.b64 {%0, %1}, %2;" : "=f"(r.x), "=f"(r.y) : "l"(v));
    return r;
}
__device__ __forceinline__ unsigned long long ffma2(unsigned long long a,
                                                    unsigned long long b,
                                                    unsigned long long c) {
    unsigned long long d;
    asm("fma.rn.f32x2 %0, %1, %2, %3;" : "=l"(d) : "l"(a), "l"(b), "l"(c));
    return d;
}

template <bool INV>
__device__ __forceinline__ void fft16(float* re, float* im) {
    {
        float tr, ti;
#define SWP(a, b) tr = re[a]; re[a] = re[b]; re[b] = tr; \
                  ti = im[a]; im[a] = im[b]; im[b] = ti;
        SWP(1, 8) SWP(2, 4) SWP(3, 12) SWP(5, 10) SWP(7, 14) SWP(11, 13)
#undef SWP
    }
    constexpr float C1 = 0.923879532511286756f;
    constexpr float S1 = 0.382683432365089772f;
    constexpr float R  = 0.707106781186547524f;
    const float C16[8] = {1.f,  C1,  R,  S1, 0.f, -S1, -R, -C1};
    const float S16[8] = {0.f,  S1,  R,  C1, 1.f,  C1,  R,  S1};
#pragma unroll
    for (int s = 0; s < 4; ++s) {
        const int h = 1 << s;
#pragma unroll
        for (int g = 0; g < 16; g += (h << 1)) {
#pragma unroll
            for (int j = 0; j < h; ++j) {
                const int m = j << (3 - s);
                const float wr = C16[m];
                const float wi = INV ? S16[m] : -S16[m];
                const int a = g + j, b = a + h;
                float tr = re[b] * wr - im[b] * wi;
                float ti = re[b] * wi + im[b] * wr;
                re[b] = re[a] - tr; im[b] = im[a] - ti;
                re[a] += tr;        im[a] += ti;
            }
        }
    }
}

// ---------------- W_fft precompute (per launch, cheap) ----------------
__global__ void bc_wfft(const float* __restrict__ W) {
    __shared__ float2 tw[256];
    __shared__ float  wv[256];
    const int ij  = blockIdx.x;      // i*16 + j
    const int tid = threadIdx.x;
    float sv, cv;
    float ang = 6.2831853071795864769f * (float)tid * (1.0f / 256.0f);  // +sign: conj folded
    sincosf(ang, &sv, &cv);
    tw[tid] = make_float2(cv, sv);
    wv[tid] = W[ij * BSZ + tid];
    __syncthreads();
    if (tid < NF) {
        float ar = 0.f, ai = 0.f;
        for (int n = 0; n < 256; ++n) {
            float2 e = tw[(tid * n) & 255];
            ar += wv[n] * e.x;
            ai += wv[n] * e.y;
        }
        g_Wc[ij * NF + tid] = __floats2half2_rn(ar * (1.f / 256.f), ai * (1.f / 256.f));
    }
}

// ---------------- main fused kernel ----------------
__global__ void __launch_bounds__(TPB, 1)
bc_main(const float* __restrict__ x, const float* __restrict__ d,
        const float* __restrict__ bias, float* __restrict__ out) {
    extern __shared__ char smem_raw[];
    __half2* Wcs = (__half2*)smem_raw;                          // 132096 B
    float2*  twf = (float2*)(smem_raw + 132096);                //   2048 B
    float*   ds  = (float*) (smem_raw + 132096 + 2048);         //  16384 B
    float2*  bufs = (float2*)(smem_raw + 150528);               //  69632 B (4 slots x 8 groups x 272)

    const int tid = threadIdx.x;
    {
        const unsigned int* src = (const unsigned int*)g_Wc;
        unsigned int* dst = (unsigned int*)Wcs;
        for (int i2 = tid; i2 < K16 * K16 * NF; i2 += TPB) dst[i2] = src[i2];
        if (tid < 256) {
            float sv, cv;
            float ang = -6.2831853071795864769f * (float)tid * (1.0f / 256.0f);
            sincosf(ang, &sv, &cv);
            twf[tid] = make_float2(cv, sv);   // e^{-2pi i m /256}
        }
        for (int i2 = tid; i2 < DIN; i2 += TPB) ds[i2] = d[i2];
    }
    __syncthreads();

    const int slot = tid >> 7;        // 0..3: independent row pipeline
    const int t128 = tid & 127;
    const int g    = t128 >> 4;       // FFT group 0..7 (pair of blocks)
    const int t    = t128 & 15;       // lane within FFT
    const int barid = slot + 1;
    float2* Zb = bufs + slot * (8 * GP);
    float2* gb = Zb + g * GP;

    float re[16], im[16];

#define BARS() asm volatile("bar.sync %0, 128;" :: "r"(barid) : "memory")

    for (int row = blockIdx.x * NSLOT + slot; row < NB; row += gridDim.x * NSLOT) {
        const float4* xrow4 = (const float4*)(x + (size_t)row * DIN);
        const float4* ds4   = (const float4*)ds;

        // ---- P0: load row (float4), multiply by d, pack into FFT tiles ----
#pragma unroll
        for (int it = 0; it < 8; ++it) {
            int c4 = t128 + (it << 7);
            float4 xv = xrow4[c4];
            float4 dv = ds4[c4];
            float v[4] = {xv.x * dv.x, xv.y * dv.y, xv.z * dv.z, xv.w * dv.w};
#pragma unroll
            for (int e = 0; e < 4; ++e) {
                int col = (c4 << 2) + e;
                int p = col >> 9;          // group (2 blocks of 256)
                int n = col & 255;
                float* dstp = (float*)(Zb + p * GP + (n & 15) * 17 + (n >> 4));
                dstp[(col >> 8) & 1] = v[e];  // even block -> re, odd -> im
            }
        }
        BARS();

        // ---- forward FFT-256, in place within each group tile ----
        // step 1: FFT16 over n2 (rows), twiddle, transpose-write
#pragma unroll
        for (int n1 = 0; n1 < 16; ++n1) {
            float2 v = gb[t * 17 + n1];
            re[n1] = v.x; im[n1] = v.y;
        }
        fft16<false>(re, im);
        __syncwarp();
#pragma unroll
        for (int k1 = 0; k1 < 16; ++k1) {
            if (k1 > 0) {
                float2 w = twf[(t * k1) & 255];
                cmul(re[k1], im[k1], w.x, w.y);
            }
            gb[k1 * 17 + t] = make_float2(re[k1], im[k1]);
        }
        __syncwarp();
        // step 2: FFT16 over n1 -> Z natural order (linear 0..255)
#pragma unroll
        for (int n2 = 0; n2 < 16; ++n2) {
            float2 v = gb[t * 17 + n2];
            re[n2] = v.x; im[n2] = v.y;
        }
        fft16<false>(re, im);
        __syncwarp();
#pragma unroll
        for (int k2 = 0; k2 < 16; ++k2)
            gb[(k2 << 4) + t] = make_float2(re[k2], im[k2]);
        BARS();

        // ---- einsum (in place, fused Hermitian unpack + repack) ----
        {
            const int f  = t128;            // 0..127
            const int mf = (256 - f) & 255;
            float xr[16], xi[16];
#pragma unroll
            for (int p = 0; p < 8; ++p) {
                float2 a = Zb[p * GP + f];
                float2 b = Zb[p * GP + mf];
                xr[2 * p]     = 0.5f * (a.x + b.x);
                xi[2 * p]     = 0.5f * (a.y - b.y);
                xr[2 * p + 1] = 0.5f * (a.y + b.y);
                xi[2 * p + 1] = 0.5f * (b.x - a.x);
            }
#pragma unroll
            for (int h = 0; h < 2; ++h) {
                unsigned long long acc1[8], acc2[8];
#pragma unroll
                for (int i = 0; i < 8; ++i) { acc1[i] = 0ull; acc2[i] = 0ull; }
#pragma unroll
                for (int j = 0; j < 16; ++j) {
                    unsigned long long xrr = pk2(xr[j], xr[j]);
                    unsigned long long xii = pk2(xi[j], xi[j]);
#pragma unroll
                    for (int i = 0; i < 8; ++i) {
                        float2 w = __half22float2(Wcs[((h * 8 + i) * 16 + j) * NF + f]);
                        unsigned long long wd = pk2(w.x, w.y);
                        acc1[i] = ffma2(xrr, wd, acc1[i]);
                        acc2[i] = ffma2(xii, wd, acc2[i]);
                    }
                }
#pragma unroll
                for (int gg = 0; gg < 4; ++gg) {
                    float2 a1 = upk2(acc1[2 * gg]),     a2 = upk2(acc2[2 * gg]);
                    float2 b1 = upk2(acc1[2 * gg + 1]), b2 = upk2(acc2[2 * gg + 1]);
                    float ar = a1.x - a2.y, ai = a1.y + a2.x;   // Y_{2g}[f]
                    float br = b1.x - b2.y, bi = b1.y + b2.x;   // Y_{2g+1}[f]
                    int g2 = h * 4 + gg;
                    Zb[g2 * GP + f] = make_float2(ar - bi, ai + br);
                    if (f > 0)
                        Zb[g2 * GP + 256 - f] = make_float2(ar + bi, br - ai);
                }
            }
            // Nyquist f=128: real spectra, 16 threads do 16 real dot products
            if (t128 < 16) {
                float xn[16];
#pragma unroll
                for (int p = 0; p < 8; ++p) {
                    float2 z = Zb[p * GP + 128];
                    xn[2 * p] = z.x; xn[2 * p + 1] = z.y;
                }
                float acc = 0.f;
#pragma unroll
                for (int j = 0; j < 16; ++j)
                    acc += xn[j] * __low2float(Wcs[(t128 * 16 + j) * NF + 128]);
                __syncwarp(0x0000FFFFu);
                ((float*)(Zb + (t128 >> 1) * GP + 128))[t128 & 1] = acc;
            }
        }
        BARS();

        // ---- inverse FFT-256, in place; add bias; store ----
        // step 1: inverse FFT16 over stride-16 subsequence, conj twiddle, transpose-write
#pragma unroll
        for (int n1 = 0; n1 < 16; ++n1) {
            float2 v = gb[(n1 << 4) + t];
            re[n1] = v.x; im[n1] = v.y;
        }
        fft16<true>(re, im);
        __syncwarp();
#pragma unroll
        for (int k1 = 0; k1 < 16; ++k1) {
            if (k1 > 0) {
                float2 w = twf[(t * k1) & 255];
                cmul(re[k1], im[k1], w.x, -w.y);   // conj twiddle
            }
            gb[k1 * 17 + t] = make_float2(re[k1], im[k1]);
        }
        __syncwarp();
        // step 2: inverse FFT16, add bias, store
#pragma unroll
        for (int n2 = 0; n2 < 16; ++n2) {
            float2 v = gb[t * 17 + n2];
            re[n2] = v.x; im[n2] = v.y;
        }
        fft16<true>(re, im);
        {
            float* orow = out + (size_t)row * DIN + (g << 9);
            const float* brow = bias + (g << 9);
#pragma unroll
            for (int k2 = 0; k2 < 16; ++k2) {
                int n = (k2 << 4) + t;
                orow[n]       = re[k2] + __ldg(brow + n);        // even block (real)
                orow[n + 256] = im[k2] + __ldg(brow + n + 256);  // odd block (imag)
            }
        }
        BARS();   // protect buffer before next iteration's P0
    }
#undef BARS
}

extern "C" void kernel_launch(void* const* d_in, const int* in_sizes, int n_in,
                              void* d_out, int out_size) {
    const float* x    = (const float*)d_in[0];
    const float* W    = (const float*)d_in[1];
    const float* d    = (const float*)d_in[2];
    const float* bias = (const float*)d_in[3];
    float* out = (float*)d_out;

    const size_t SMEM = 132096 + 2048 + 16384 + (size_t)NSLOT * 8 * GP * sizeof(float2); // 220160
    cudaFuncSetAttribute(bc_main, cudaFuncAttributeMaxDynamicSharedMemorySize, (int)SMEM);

    bc_wfft<<<K16 * K16, 256>>>(W);
    bc_main<<<152, TPB, SMEM>>>(x, d, bias, out);
    (void)in_sizes; (void)n_in; (void)out_size;
}

// round 7
// speedup vs baseline: 1.3844x; 1.0020x over previous
#include <cuda_runtime.h>
#include <cuda_fp16.h>
#include <stdint.h>
#include <math.h>

// BlockCirculant via FFT:  out = ifft( fft(x*d blocks) * conj(fft(W)) ) + bias
// 4 independent 128-thread row pipelines per CTA (named barriers), in-place
// FFT-256 (16x16 Cooley-Tukey), einsum fused with Hermitian unpack/repack,
// rotated [f][ij] fp16 W layout with LDS.128, packed f32x2 FFMA, x prefetch.

#define K16   16
#define BSZ   256
#define NF    129        // Hermitian frequencies 0..128
#define DIN   4096
#define NB    8192
#define GP    272        // float2 per FFT group scratch (16*17)
#define NSLOT 4
#define TPB   512

// Wf[f*256 + ((ij + 4f) & 255)] = conj(FFT(W[i,j,:]))[f] / 256   (half2)
__device__ __half2 g_Wf[NF * 256];

__device__ __forceinline__ void cmul(float& xr, float& xi, float wr, float wi) {
    float tr = xr * wr - xi * wi;
    xi       = xr * wi + xi * wr;
    xr       = tr;
}

// ---- packed fp32x2 helpers (Blackwell FFMA2) ----
__device__ __forceinline__ unsigned long long pk2(float lo, float hi) {
    unsigned long long r;
    asm("mov.b64 %0, {%1, %2};" : "=l"(r) : "f"(lo), "f"(hi));
    return r;
}
__device__ __forceinline__ float2 upk2(unsigned long long v) {
    float2 r;
    asm("mov.b64 {%0, %1}, %2;" : "=f"(r.x), "=f"(r.y) : "l"(v));
    return r;
}
__device__ __forceinline__ unsigned long long ffma2(unsigned long long a,
                                                    unsigned long long b,
                                                    unsigned long long c) {
    unsigned long long d;
    asm("fma.rn.f32x2 %0, %1, %2, %3;" : "=l"(d) : "l"(a), "l"(b), "l"(c));
    return d;
}

template <bool INV>
__device__ __forceinline__ void fft16(float* re, float* im) {
    {
        float tr, ti;
#define SWP(a, b) tr = re[a]; re[a] = re[b]; re[b] = tr; \
                  ti = im[a]; im[a] = im[b]; im[b] = ti;
        SWP(1, 8) SWP(2, 4) SWP(3, 12) SWP(5, 10) SWP(7, 14) SWP(11, 13)
#undef SWP
    }
    constexpr float C1 = 0.923879532511286756f;
    constexpr float S1 = 0.382683432365089772f;
    constexpr float R  = 0.707106781186547524f;
    const float C16[8] = {1.f,  C1,  R,  S1, 0.f, -S1, -R, -C1};
    const float S16[8] = {0.f,  S1,  R,  C1, 1.f,  C1,  R,  S1};
#pragma unroll
    for (int s = 0; s < 4; ++s) {
        const int h = 1 << s;
#pragma unroll
        for (int g = 0; g < 16; g += (h << 1)) {
#pragma unroll
            for (int j = 0; j < h; ++j) {
                const int m = j << (3 - s);
                const float wr = C16[m];
                const float wi = INV ? S16[m] : -S16[m];
                const int a = g + j, b = a + h;
                float tr = re[b] * wr - im[b] * wi;
                float ti = re[b] * wi + im[b] * wr;
                re[b] = re[a] - tr; im[b] = im[a] - ti;
                re[a] += tr;        im[a] += ti;
            }
        }
    }
}

// ---------------- W_fft precompute (per launch, cheap) ----------------
__global__ void bc_wfft(const float* __restrict__ W) {
    __shared__ float2 tw[256];
    __shared__ float  wv[256];
    const int ij  = blockIdx.x;      // i*16 + j
    const int tid = threadIdx.x;
    float sv, cv;
    float ang = 6.2831853071795864769f * (float)tid * (1.0f / 256.0f);  // +sign: conj folded
    sincosf(ang, &sv, &cv);
    tw[tid] = make_float2(cv, sv);
    wv[tid] = W[ij * BSZ + tid];
    __syncthreads();
    if (tid < NF) {
        float ar = 0.f, ai = 0.f;
        for (int n = 0; n < 256; ++n) {
            float2 e = tw[(tid * n) & 255];
            ar += wv[n] * e.x;
            ai += wv[n] * e.y;
        }
        // rotated layout: position (ij + 4f) & 255 within row f
        g_Wf[tid * 256 + ((ij + 4 * tid) & 255)] =
            __floats2half2_rn(ar * (1.f / 256.f), ai * (1.f / 256.f));
    }
}

// ---------------- main fused kernel ----------------
__global__ void __launch_bounds__(TPB, 1)
bc_main(const float* __restrict__ x, const float* __restrict__ d,
        const float* __restrict__ bias, float* __restrict__ out) {
    extern __shared__ char smem_raw[];
    __half2* Wcs = (__half2*)smem_raw;                          // 132096 B  (129*256 half2)
    float2*  twf = (float2*)(smem_raw + 132096);                //   2048 B
    float*   ds  = (float*) (smem_raw + 132096 + 2048);         //  16384 B
    float2*  bufs = (float2*)(smem_raw + 150528);               //  69632 B (4 slots x 8 groups x 272)

    const int tid = threadIdx.x;
    {
        const unsigned int* src = (const unsigned int*)g_Wf;
        unsigned int* dst = (unsigned int*)Wcs;
        for (int i2 = tid; i2 < NF * 256; i2 += TPB) dst[i2] = src[i2];
        if (tid < 256) {
            float sv, cv;
            float ang = -6.2831853071795864769f * (float)tid * (1.0f / 256.0f);
            sincosf(ang, &sv, &cv);
            twf[tid] = make_float2(cv, sv);   // e^{-2pi i m /256}
        }
        for (int i2 = tid; i2 < DIN; i2 += TPB) ds[i2] = d[i2];
    }
    __syncthreads();

    const int slot = tid >> 7;        // 0..3: independent row pipeline
    const int t128 = tid & 127;
    const int g    = t128 >> 4;       // FFT group 0..7 (pair of blocks)
    const int t    = t128 & 15;       // lane within FFT
    const int barid = slot + 1;
    float2* Zb = bufs + slot * (8 * GP);
    float2* gb = Zb + g * GP;
    const float4* ds4 = (const float4*)ds;

    float re[16], im[16];
    float4 xv[8];

#define BARS() asm volatile("bar.sync %0, 128;" :: "r"(barid) : "memory")

    const int rstride = gridDim.x * NSLOT;
    int row = blockIdx.x * NSLOT + slot;
    if (row < NB) {
        const float4* xr4 = (const float4*)(x + (size_t)row * DIN);
#pragma unroll
        for (int it = 0; it < 8; ++it) xv[it] = xr4[t128 + (it << 7)];
    }

    for (; row < NB; row += rstride) {
        // ---- P0: scatter prefetched row (times d) into FFT tiles ----
#pragma unroll
        for (int it = 0; it < 8; ++it) {
            int c4 = t128 + (it << 7);
            float4 dv = ds4[c4];
            float v[4] = {xv[it].x * dv.x, xv[it].y * dv.y,
                          xv[it].z * dv.z, xv[it].w * dv.w};
#pragma unroll
            for (int e = 0; e < 4; ++e) {
                int col = (c4 << 2) + e;
                int p = col >> 9;          // group (2 blocks of 256)
                int n = col & 255;
                float* dstp = (float*)(Zb + p * GP + (n & 15) * 17 + (n >> 4));
                dstp[(col >> 8) & 1] = v[e];  // even block -> re, odd -> im
            }
        }
        BARS();

        // ---- prefetch next row's x (latency hidden behind this row's compute) ----
        {
            int nrow = row + rstride;
            if (nrow < NB) {
                const float4* xr4 = (const float4*)(x + (size_t)nrow * DIN);
#pragma unroll
                for (int it = 0; it < 8; ++it) xv[it] = xr4[t128 + (it << 7)];
            }
        }

        // ---- forward FFT-256, in place within each group tile ----
#pragma unroll
        for (int n1 = 0; n1 < 16; ++n1) {
            float2 v = gb[t * 17 + n1];
            re[n1] = v.x; im[n1] = v.y;
        }
        fft16<false>(re, im);
        __syncwarp();
#pragma unroll
        for (int k1 = 0; k1 < 16; ++k1) {
            if (k1 > 0) {
                float2 w = twf[(t * k1) & 255];
                cmul(re[k1], im[k1], w.x, w.y);
            }
            gb[k1 * 17 + t] = make_float2(re[k1], im[k1]);
        }
        __syncwarp();
#pragma unroll
        for (int n2 = 0; n2 < 16; ++n2) {
            float2 v = gb[t * 17 + n2];
            re[n2] = v.x; im[n2] = v.y;
        }
        fft16<false>(re, im);
        __syncwarp();
#pragma unroll
        for (int k2 = 0; k2 < 16; ++k2)
            gb[(k2 << 4) + t] = make_float2(re[k2], im[k2]);
        BARS();

        // ---- einsum (in place, fused Hermitian unpack + repack) ----
        {
            const int f  = t128;            // 0..127
            const int mf = (256 - f) & 255;
            unsigned long long xrr[16], xii[16];
#pragma unroll
            for (int p = 0; p < 8; ++p) {
                float2 a = Zb[p * GP + f];
                float2 b = Zb[p * GP + mf];
                float xr0 = 0.5f * (a.x + b.x), xi0 = 0.5f * (a.y - b.y);
                float xr1 = 0.5f * (a.y + b.y), xi1 = 0.5f * (b.x - a.x);
                xrr[2 * p]     = pk2(xr0, xr0);  xii[2 * p]     = pk2(xi0, xi0);
                xrr[2 * p + 1] = pk2(xr1, xr1);  xii[2 * p + 1] = pk2(xi1, xi1);
            }
            const uint4* W4 = ((const uint4*)Wcs) + f * 64;   // row f: 256 half2 = 64 uint4
#pragma unroll
            for (int gg = 0; gg < 8; ++gg) {
                unsigned long long A1 = 0ull, A2 = 0ull, B1 = 0ull, B2 = 0ull;
                const int ia = 2 * gg, ib = 2 * gg + 1;
#pragma unroll
                for (int jc = 0; jc < 4; ++jc) {
                    uint4 wa = W4[(ia * 4 + jc + f) & 63];
                    uint4 wb = W4[(ib * 4 + jc + f) & 63];
                    unsigned int wax[4] = {wa.x, wa.y, wa.z, wa.w};
                    unsigned int wbx[4] = {wb.x, wb.y, wb.z, wb.w};
#pragma unroll
                    for (int e = 0; e < 4; ++e) {
                        const int j = jc * 4 + e;
                        float2 w1 = __half22float2(*(__half2*)&wax[e]);
                        unsigned long long wd1 = pk2(w1.x, w1.y);
                        A1 = ffma2(xrr[j], wd1, A1);
                        A2 = ffma2(xii[j], wd1, A2);
                        float2 w2 = __half22float2(*(__half2*)&wbx[e]);
                        unsigned long long wd2 = pk2(w2.x, w2.y);
                        B1 = ffma2(xrr[j], wd2, B1);
                        B2 = ffma2(xii[j], wd2, B2);
                    }
                }
                float2 a1 = upk2(A1), a2 = upk2(A2);
                float2 b1 = upk2(B1), b2 = upk2(B2);
                float ar = a1.x - a2.y, ai = a1.y + a2.x;   // Y_{2gg}[f]
                float br = b1.x - b2.y, bi = b1.y + b2.x;   // Y_{2gg+1}[f]
                Zb[gg * GP + f] = make_float2(ar - bi, ai + br);
                if (f > 0)
                    Zb[gg * GP + 256 - f] = make_float2(ar + bi, br - ai);
            }
            // Nyquist f=128: real spectra, 16 threads do 16 real dot products
            if (t128 < 16) {
                float xn[16];
#pragma unroll
                for (int p = 0; p < 8; ++p) {
                    float2 z = Zb[p * GP + 128];
                    xn[2 * p] = z.x; xn[2 * p + 1] = z.y;
                }
                float acc = 0.f;
#pragma unroll
                for (int j = 0; j < 16; ++j)
                    acc += xn[j] * __low2float(Wcs[128 * 256 + t128 * 16 + j]);
                __syncwarp(0x0000FFFFu);
                ((float*)(Zb + (t128 >> 1) * GP + 128))[t128 & 1] = acc;
            }
        }
        BARS();

        // ---- inverse FFT-256, in place; add bias; store ----
#pragma unroll
        for (int n1 = 0; n1 < 16; ++n1) {
            float2 v = gb[(n1 << 4) + t];
            re[n1] = v.x; im[n1] = v.y;
        }
        fft16<true>(re, im);
        __syncwarp();
#pragma unroll
        for (int k1 = 0; k1 < 16; ++k1) {
            if (k1 > 0) {
                float2 w = twf[(t * k1) & 255];
                cmul(re[k1], im[k1], w.x, -w.y);   // conj twiddle
            }
            gb[k1 * 17 + t] = make_float2(re[k1], im[k1]);
        }
        __syncwarp();
#pragma unroll
        for (int n2 = 0; n2 < 16; ++n2) {
            float2 v = gb[t * 17 + n2];
            re[n2] = v.x; im[n2] = v.y;
        }
        fft16<true>(re, im);
        {
            float* orow = out + (size_t)row * DIN + (g << 9);
            const float* brow = bias + (g << 9);
#pragma unroll
            for (int k2 = 0; k2 < 16; ++k2) {
                int n = (k2 << 4) + t;
                orow[n]       = re[k2] + __ldg(brow + n);        // even block (real)
                orow[n + 256] = im[k2] + __ldg(brow + n + 256);  // odd block (imag)
            }
        }
        BARS();   // protect buffer before next iteration's P0
    }
#undef BARS
}

extern "C" void kernel_launch(void* const* d_in, const int* in_sizes, int n_in,
                              void* d_out, int out_size) {
    const float* x    = (const float*)d_in[0];
    const float* W    = (const float*)d_in[1];
    const float* d    = (const float*)d_in[2];
    const float* bias = (const float*)d_in[3];
    float* out = (float*)d_out;

    const size_t SMEM = 132096 + 2048 + 16384 + (size_t)NSLOT * 8 * GP * sizeof(float2); // 220160
    cudaFuncSetAttribute(bc_main, cudaFuncAttributeMaxDynamicSharedMemorySize, (int)SMEM);

    bc_wfft<<<K16 * K16, 256>>>(W);
    bc_main<<<152, TPB, SMEM>>>(x, d, bias, out);
    (void)in_sizes; (void)n_in; (void)out_size;
}

// round 12
// speedup vs baseline: 1.4867x; 1.0739x over previous
#include <cuda_runtime.h>
#include <cuda_fp16.h>
#include <stdint.h>
#include <math.h>

// BlockCirculant via FFT:  out = ifft( fft(x*d blocks) * conj(fft(W)) ) + bias
// 4 independent 128-thread row pipelines per CTA (named barriers), in-place
// FFT-256 (16x16 Cooley-Tukey). ALL intermediate buffers in fp16 (half2 per
// complex) to halve shared-memory data-path wavefronts; math stays fp32.

#define K16   16
#define BSZ   256
#define NF    129        // Hermitian frequencies 0..128
#define DIN   4096
#define NB    8192
#define GP    272        // half2 per FFT group scratch (16*17)
#define NSLOT 4
#define TPB   512

// Wf[f*256 + ((ij + 4f) & 255)] = conj(FFT(W[i,j,:]))[f] / 256   (half2)
__device__ __half2 g_Wf[NF * 256];

__device__ __forceinline__ void cmul(float& xr, float& xi, float wr, float wi) {
    float tr = xr * wr - xi * wi;
    xi       = xr * wi + xi * wr;
    xr       = tr;
}

// ---- packed fp32x2 helpers (Blackwell FFMA2) ----
__device__ __forceinline__ unsigned long long pk2(float lo, float hi) {
    unsigned long long r;
    asm("mov.b64 %0, {%1, %2};" : "=l"(r) : "f"(lo), "f"(hi));
    return r;
}
__device__ __forceinline__ float2 upk2(unsigned long long v) {
    float2 r;
    asm("mov.b64 {%0, %1}, %2;" : "=f"(r.x), "=f"(r.y) : "l"(v));
    return r;
}
__device__ __forceinline__ unsigned long long ffma2(unsigned long long a,
                                                    unsigned long long b,
                                                    unsigned long long c) {
    unsigned long long d;
    asm("fma.rn.f32x2 %0, %1, %2, %3;" : "=l"(d) : "l"(a), "l"(b), "l"(c));
    return d;
}

template <bool INV>
__device__ __forceinline__ void fft16(float* re, float* im) {
    {
        float tr, ti;
#define SWP(a, b) tr = re[a]; re[a] = re[b]; re[b] = tr; \
                  ti = im[a]; im[a] = im[b]; im[b] = ti;
        SWP(1, 8) SWP(2, 4) SWP(3, 12) SWP(5, 10) SWP(7, 14) SWP(11, 13)
#undef SWP
    }
    constexpr float C1 = 0.923879532511286756f;
    constexpr float S1 = 0.382683432365089772f;
    constexpr float R  = 0.707106781186547524f;
    const float C16[8] = {1.f,  C1,  R,  S1, 0.f, -S1, -R, -C1};
    const float S16[8] = {0.f,  S1,  R,  C1, 1.f,  C1,  R,  S1};
#pragma unroll
    for (int s = 0; s < 4; ++s) {
        const int h = 1 << s;
#pragma unroll
        for (int g = 0; g < 16; g += (h << 1)) {
#pragma unroll
            for (int j = 0; j < h; ++j) {
                const int m = j << (3 - s);
                const float wr = C16[m];
                const float wi = INV ? S16[m] : -S16[m];
                const int a = g + j, b = a + h;
                float tr = re[b] * wr - im[b] * wi;
                float ti = re[b] * wi + im[b] * wr;
                re[b] = re[a] - tr; im[b] = im[a] - ti;
                re[a] += tr;        im[a] += ti;
            }
        }
    }
}

// ---------------- W_fft precompute (per launch, cheap) ----------------
__global__ void bc_wfft(const float* __restrict__ W) {
    __shared__ float2 tw[256];
    __shared__ float  wv[256];
    const int ij  = blockIdx.x;      // i*16 + j
    const int tid = threadIdx.x;
    float sv, cv;
    float ang = 6.2831853071795864769f * (float)tid * (1.0f / 256.0f);  // +sign: conj folded
    sincosf(ang, &sv, &cv);
    tw[tid] = make_float2(cv, sv);
    wv[tid] = W[ij * BSZ + tid];
    __syncthreads();
    if (tid < NF) {
        float ar = 0.f, ai = 0.f;
        for (int n = 0; n < 256; ++n) {
            float2 e = tw[(tid * n) & 255];
            ar += wv[n] * e.x;
            ai += wv[n] * e.y;
        }
        // rotated layout: position (ij + 4f) & 255 within row f
        g_Wf[tid * 256 + ((ij + 4 * tid) & 255)] =
            __floats2half2_rn(ar * (1.f / 256.f), ai * (1.f / 256.f));
    }
}

// ---------------- main fused kernel ----------------
__global__ void __launch_bounds__(TPB, 1)
bc_main(const float* __restrict__ x, const float* __restrict__ d,
        const float* __restrict__ bias, float* __restrict__ out) {
    extern __shared__ char smem_raw[];
    __half2* Wcs = (__half2*)smem_raw;                          // 132096 B  (129*256 half2)
    float2*  twf = (float2*)(smem_raw + 132096);                //   2048 B
    float*   ds  = (float*) (smem_raw + 132096 + 2048);         //  16384 B
    __half2* bufs = (__half2*)(smem_raw + 150528);              //  34816 B (4 slots x 8 groups x 272)

    const int tid = threadIdx.x;
    {
        const unsigned int* src = (const unsigned int*)g_Wf;
        unsigned int* dst = (unsigned int*)Wcs;
        for (int i2 = tid; i2 < NF * 256; i2 += TPB) dst[i2] = src[i2];
        if (tid < 256) {
            float sv, cv;
            float ang = -6.2831853071795864769f * (float)tid * (1.0f / 256.0f);
            sincosf(ang, &sv, &cv);
            twf[tid] = make_float2(cv, sv);   // e^{-2pi i m /256}
        }
        for (int i2 = tid; i2 < DIN; i2 += TPB) ds[i2] = d[i2];
    }
    __syncthreads();

    const int slot = tid >> 7;        // 0..3: independent row pipeline
    const int t128 = tid & 127;
    const int g    = t128 >> 4;       // FFT group 0..7 (pair of blocks)
    const int t    = t128 & 15;       // lane within FFT
    const int barid = slot + 1;
    __half2* Zb = bufs + slot * (8 * GP);
    __half2* gb = Zb + g * GP;
    const float4* ds4 = (const float4*)ds;

    float re[16], im[16];
    float4 xv[8];

#define BARS() asm volatile("bar.sync %0, 128;" :: "r"(barid) : "memory")

    const int rstride = gridDim.x * NSLOT;
    int row = blockIdx.x * NSLOT + slot;
    if (row < NB) {
        const float4* xr4 = (const float4*)(x + (size_t)row * DIN);
#pragma unroll
        for (int it = 0; it < 8; ++it) xv[it] = xr4[t128 + (it << 7)];
    }

    for (; row < NB; row += rstride) {
        // ---- P0: scatter prefetched row (times d) into FFT tiles (fp16) ----
#pragma unroll
        for (int it = 0; it < 8; ++it) {
            int c4 = t128 + (it << 7);
            float4 dv = ds4[c4];
            float v[4] = {xv[it].x * dv.x, xv[it].y * dv.y,
                          xv[it].z * dv.z, xv[it].w * dv.w};
#pragma unroll
            for (int e = 0; e < 4; ++e) {
                int col = (c4 << 2) + e;
                int p = col >> 9;          // group (2 blocks of 256)
                int n = col & 255;
                __half* dstp = (__half*)(Zb + p * GP + (n & 15) * 17 + (n >> 4));
                dstp[(col >> 8) & 1] = __float2half(v[e]);  // even blk -> re, odd -> im
            }
        }
        BARS();

        // ---- prefetch next row's x ----
        {
            int nrow = row + rstride;
            if (nrow < NB) {
                const float4* xr4 = (const float4*)(x + (size_t)nrow * DIN);
#pragma unroll
                for (int it = 0; it < 8; ++it) xv[it] = xr4[t128 + (it << 7)];
            }
        }

        // ---- forward FFT-256, in place within each group tile ----
#pragma unroll
        for (int n1 = 0; n1 < 16; ++n1) {
            float2 v = __half22float2(gb[t * 17 + n1]);
            re[n1] = v.x; im[n1] = v.y;
        }
        fft16<false>(re, im);
        __syncwarp();
#pragma unroll
        for (int k1 = 0; k1 < 16; ++k1) {
            if (k1 > 0) {
                float2 w = twf[(t * k1) & 255];
                cmul(re[k1], im[k1], w.x, w.y);
            }
            gb[k1 * 17 + t] = __floats2half2_rn(re[k1], im[k1]);
        }
        __syncwarp();
#pragma unroll
        for (int n2 = 0; n2 < 16; ++n2) {
            float2 v = __half22float2(gb[t * 17 + n2]);
            re[n2] = v.x; im[n2] = v.y;
        }
        fft16<false>(re, im);
        __syncwarp();
#pragma unroll
        for (int k2 = 0; k2 < 16; ++k2)
            gb[(k2 << 4) + t] = __floats2half2_rn(re[k2], im[k2]);
        BARS();

        // ---- einsum (in place, fused Hermitian unpack + repack) ----
        {
            const int f  = t128;            // 0..127
            const int mf = (256 - f) & 255;
            unsigned long long xrr[16], xii[16];
#pragma unroll
            for (int p = 0; p < 8; ++p) {
                float2 a = __half22float2(Zb[p * GP + f]);
                float2 b = __half22float2(Zb[p * GP + mf]);
                float xr0 = 0.5f * (a.x + b.x), xi0 = 0.5f * (a.y - b.y);
                float xr1 = 0.5f * (a.y + b.y), xi1 = 0.5f * (b.x - a.x);
                xrr[2 * p]     = pk2(xr0, xr0);  xii[2 * p]     = pk2(xi0, xi0);
                xrr[2 * p + 1] = pk2(xr1, xr1);  xii[2 * p + 1] = pk2(xi1, xi1);
            }
            const uint4* W4 = ((const uint4*)Wcs) + f * 64;   // row f: 256 half2 = 64 uint4
#pragma unroll
            for (int gg = 0; gg < 8; ++gg) {
                unsigned long long A1 = 0ull, A2 = 0ull, B1 = 0ull, B2 = 0ull;
                const int ia = 2 * gg, ib = 2 * gg + 1;
#pragma unroll
                for (int jc = 0; jc < 4; ++jc) {
                    uint4 wa = W4[(ia * 4 + jc + f) & 63];
                    uint4 wb = W4[(ib * 4 + jc + f) & 63];
                    unsigned int wax[4] = {wa.x, wa.y, wa.z, wa.w};
                    unsigned int wbx[4] = {wb.x, wb.y, wb.z, wb.w};
#pragma unroll
                    for (int e = 0; e < 4; ++e) {
                        const int j = jc * 4 + e;
                        float2 w1 = __half22float2(*(__half2*)&wax[e]);
                        unsigned long long wd1 = pk2(w1.x, w1.y);
                        A1 = ffma2(xrr[j], wd1, A1);
                        A2 = ffma2(xii[j], wd1, A2);
                        float2 w2 = __half22float2(*(__half2*)&wbx[e]);
                        unsigned long long wd2 = pk2(w2.x, w2.y);
                        B1 = ffma2(xrr[j], wd2, B1);
                        B2 = ffma2(xii[j], wd2, B2);
                    }
                }
                float2 a1 = upk2(A1), a2 = upk2(A2);
                float2 b1 = upk2(B1), b2 = upk2(B2);
                float ar = a1.x - a2.y, ai = a1.y + a2.x;   // Y_{2gg}[f]
                float br = b1.x - b2.y, bi = b1.y + b2.x;   // Y_{2gg+1}[f]
                Zb[gg * GP + f] = __floats2half2_rn(ar - bi, ai + br);
                if (f > 0)
                    Zb[gg * GP + 256 - f] = __floats2half2_rn(ar + bi, br - ai);
            }
            // Nyquist f=128: real spectra, 16 threads do 16 real dot products
            if (t128 < 16) {
                float xn[16];
#pragma unroll
                for (int p = 0; p < 8; ++p) {
                    float2 z = __half22float2(Zb[p * GP + 128]);
                    xn[2 * p] = z.x; xn[2 * p + 1] = z.y;
                }
                float acc = 0.f;
#pragma unroll
                for (int j = 0; j < 16; ++j)
                    acc += xn[j] * __low2float(Wcs[128 * 256 + t128 * 16 + j]);
                __syncwarp(0x0000FFFFu);
                ((__half*)(Zb + (t128 >> 1) * GP + 128))[t128 & 1] = __float2half(acc);
            }
        }
        BARS();

        // ---- inverse FFT-256, in place; add bias; store ----
#pragma unroll
        for (int n1 = 0; n1 < 16; ++n1) {
            float2 v = __half22float2(gb[(n1 << 4) + t]);
            re[n1] = v.x; im[n1] = v.y;
        }
        fft16<true>(re, im);
        __syncwarp();
#pragma unroll
        for (int k1 = 0; k1 < 16; ++k1) {
            if (k1 > 0) {
                float2 w = twf[(t * k1) & 255];
                cmul(re[k1], im[k1], w.x, -w.y);   // conj twiddle
            }
            gb[k1 * 17 + t] = __floats2half2_rn(re[k1], im[k1]);
        }
        __syncwarp();
#pragma unroll
        for (int n2 = 0; n2 < 16; ++n2) {
            float2 v = __half22float2(gb[t * 17 + n2]);
            re[n2] = v.x; im[n2] = v.y;
        }
        fft16<true>(re, im);
        {
            float* orow = out + (size_t)row * DIN + (g << 9);
            const float* brow = bias + (g << 9);
#pragma unroll
            for (int k2 = 0; k2 < 16; ++k2) {
                int n = (k2 << 4) + t;
                orow[n]       = re[k2] + __ldg(brow + n);        // even block (real)
                orow[n + 256] = im[k2] + __ldg(brow + n + 256);  // odd block (imag)
            }
        }
        BARS();   // protect buffer before next iteration's P0
    }
#undef BARS
}

extern "C" void kernel_launch(void* const* d_in, const int* in_sizes, int n_in,
                              void* d_out, int out_size) {
    const float* x    = (const float*)d_in[0];
    const float* W    = (const float*)d_in[1];
    const float* d    = (const float*)d_in[2];
    const float* bias = (const float*)d_in[3];
    float* out = (float*)d_out;

    const size_t SMEM = 132096 + 2048 + 16384 + (size_t)NSLOT * 8 * GP * sizeof(__half2); // 185344
    cudaFuncSetAttribute(bc_main, cudaFuncAttributeMaxDynamicSharedMemorySize, (int)SMEM);

    bc_wfft<<<K16 * K16, 256>>>(W);
    bc_main<<<152, TPB, SMEM>>>(x, d, bias, out);
    (void)in_sizes; (void)n_in; (void)out_size;
}